// round 1
// baseline (speedup 1.0000x reference)
#include <cuda_runtime.h>
#include <math.h>

// NT-Xent loss, fused streaming-softmax formulation.
// loss_i = m_i + log(sum_j exp(sim_ij - m_i)) - sim[i, target(i)]
// where sim = (z z^T)/T with diag excluded, target(i) = (i+B) mod 2B.
// Output: mean over all 8192 rows (single f32 scalar).

#define NTOT 8192
#define BHALF 4096
#define DK 128
#define BI 64
#define BJ 128
#define SQRT_INV_T 2.2360679774997896f  // sqrt(1/0.2); folds temperature into z

__device__ float g_z[NTOT * DK];     // concatenated, pre-scaled z
__device__ float g_loss[NTOT];       // per-row losses

// ---------------------------------------------------------------------------
// Kernel 1: concat z1,z2 and scale by sqrt(1/T)
// ---------------------------------------------------------------------------
__global__ void prep_kernel(const float* __restrict__ z1,
                            const float* __restrict__ z2) {
    int idx = blockIdx.x * blockDim.x + threadIdx.x;   // float4 index
    const int half4 = BHALF * DK / 4;
    float4 v;
    if (idx < half4) v = ((const float4*)z1)[idx];
    else             v = ((const float4*)z2)[idx - half4];
    v.x *= SQRT_INV_T; v.y *= SQRT_INV_T; v.z *= SQRT_INV_T; v.w *= SQRT_INV_T;
    ((float4*)g_z)[idx] = v;
}

// ---------------------------------------------------------------------------
// Kernel 2: fused GEMM + online softmax statistics per row.
// Grid: NTOT/BI = 128 CTAs, 256 threads each.
// smem: zi [DK][BI] (k-major) + zj [DK][BJ] (k-major) = 96 KB.
// Thread (tx,ty) (16x16) owns a 4-row x 8-col accumulator block.
// ---------------------------------------------------------------------------
__global__ __launch_bounds__(256) void ntxent_kernel() {
    extern __shared__ float sm[];
    float* zi = sm;               // [DK][BI], k-major
    float* zj = sm + DK * BI;     // [DK][BJ], k-major

    const int tid = threadIdx.x;
    const int tx = tid & 15;
    const int ty = tid >> 4;
    const int i0 = blockIdx.x * BI;

    // Load zi tile (transpose to k-major). 64 rows x 128 K.
    #pragma unroll
    for (int it = 0; it < (BI * DK / 4) / 256; ++it) {
        int u = tid + it * 256;
        int r = u & (BI - 1);       // lane-varying row -> conflict-free STS
        int kq = u >> 6;
        float4 v = *(const float4*)&g_z[(i0 + r) * DK + kq * 4];
        zi[(kq * 4 + 0) * BI + r] = v.x;
        zi[(kq * 4 + 1) * BI + r] = v.y;
        zi[(kq * 4 + 2) * BI + r] = v.z;
        zi[(kq * 4 + 3) * BI + r] = v.w;
    }

    float runm[4], runs[4], tval[4];
    #pragma unroll
    for (int r = 0; r < 4; ++r) {
        runm[r] = -INFINITY; runs[r] = 0.0f; tval[r] = -INFINITY;
    }

    for (int jt = 0; jt < NTOT / BJ; ++jt) {
        int j0 = jt * BJ;
        __syncthreads();  // previous tile's compute done before overwrite
        #pragma unroll
        for (int it = 0; it < (BJ * DK / 4) / 256; ++it) {
            int u = tid + it * 256;
            int c = u & (BJ - 1);   // lane-varying col -> conflict-free STS
            int kq = u >> 7;
            float4 v = *(const float4*)&g_z[(j0 + c) * DK + kq * 4];
            zj[(kq * 4 + 0) * BJ + c] = v.x;
            zj[(kq * 4 + 1) * BJ + c] = v.y;
            zj[(kq * 4 + 2) * BJ + c] = v.z;
            zj[(kq * 4 + 3) * BJ + c] = v.w;
        }
        __syncthreads();

        float acc[4][8];
        #pragma unroll
        for (int r = 0; r < 4; ++r)
            #pragma unroll
            for (int c = 0; c < 8; ++c) acc[r][c] = 0.0f;

        #pragma unroll 4
        for (int k = 0; k < DK; ++k) {
            float4 a  = *(const float4*)&zi[k * BI + ty * 4];
            float4 b0 = *(const float4*)&zj[k * BJ + tx * 8];
            float4 b1 = *(const float4*)&zj[k * BJ + tx * 8 + 4];
            float av[4] = {a.x, a.y, a.z, a.w};
            float bv[8] = {b0.x, b0.y, b0.z, b0.w, b1.x, b1.y, b1.z, b1.w};
            #pragma unroll
            for (int r = 0; r < 4; ++r)
                #pragma unroll
                for (int c = 0; c < 8; ++c)
                    acc[r][c] = fmaf(av[r], bv[c], acc[r][c]);
        }

        // Online softmax update for this tile.
        #pragma unroll
        for (int r = 0; r < 4; ++r) {
            int i   = i0 + ty * 4 + r;
            int tgt = (i + BHALF) & (NTOT - 1);
            float vv[8];
            float tmax = -INFINITY;
            #pragma unroll
            for (int c = 0; c < 8; ++c) {
                int j = j0 + tx * 8 + c;
                float v = acc[r][c];
                if (j == i)   v = -INFINITY;   // diag mask (== finfo.min in ref)
                if (j == tgt) tval[r] = v;     // target logit (tgt != i always)
                vv[c] = v;
                tmax = fmaxf(tmax, v);
            }
            float nm = fmaxf(runm[r], tmax);
            float s  = runs[r] * __expf(runm[r] - nm);  // 0*exp(-inf)=0 on first tile
            #pragma unroll
            for (int c = 0; c < 8; ++c) s += __expf(vv[c] - nm);
            runm[r] = nm;
            runs[r] = s;
        }
    }

    // Cross-thread reduction: the 16 lanes sharing a row are contiguous in-warp.
    #pragma unroll
    for (int off = 8; off >= 1; off >>= 1) {
        #pragma unroll
        for (int r = 0; r < 4; ++r) {
            float m2 = __shfl_xor_sync(0xffffffffu, runm[r], off);
            float s2 = __shfl_xor_sync(0xffffffffu, runs[r], off);
            float t2 = __shfl_xor_sync(0xffffffffu, tval[r], off);
            float nm = fmaxf(runm[r], m2);
            runs[r] = runs[r] * __expf(runm[r] - nm) + s2 * __expf(m2 - nm);
            runm[r] = nm;
            tval[r] = fmaxf(tval[r], t2);
        }
    }
    if (tx == 0) {
        #pragma unroll
        for (int r = 0; r < 4; ++r) {
            int i = i0 + ty * 4 + r;
            g_loss[i] = runm[r] + logf(runs[r]) - tval[r];
        }
    }
}

// ---------------------------------------------------------------------------
// Kernel 3: deterministic mean reduction (fixed order, no float atomics).
// ---------------------------------------------------------------------------
__global__ void reduce_kernel(float* __restrict__ out) {
    __shared__ float smr[256];
    int tid = threadIdx.x;
    float s = 0.0f;
    for (int i = tid; i < NTOT; i += 256) s += g_loss[i];
    smr[tid] = s;
    __syncthreads();
    for (int st = 128; st > 0; st >>= 1) {
        if (tid < st) smr[tid] += smr[tid + st];
        __syncthreads();
    }
    if (tid == 0) out[0] = smr[0] / (float)NTOT;
}

// ---------------------------------------------------------------------------
extern "C" void kernel_launch(void* const* d_in, const int* in_sizes, int n_in,
                              void* d_out, int out_size) {
    const float* z1 = (const float*)d_in[0];
    const float* z2 = (const float*)d_in[1];
    float* out = (float*)d_out;

    const int smem_bytes = (DK * BI + DK * BJ) * (int)sizeof(float);  // 96 KB
    cudaFuncSetAttribute(ntxent_kernel,
                         cudaFuncAttributeMaxDynamicSharedMemorySize, smem_bytes);

    prep_kernel<<<(NTOT * DK / 4) / 256, 256>>>(z1, z2);
    ntxent_kernel<<<NTOT / BI, 256, smem_bytes>>>();
    reduce_kernel<<<1, 256>>>(out);
}

// round 5
// speedup vs baseline: 8.5238x; 8.5238x over previous
#include <cuda_runtime.h>
#include <cuda_bf16.h>
#include <math.h>
#include <stdint.h>

// NT-Xent loss: fused bf16 mma.sync GEMM + streaming base-2 softmax.
// sim2[i][j] = (z_i.z_j) * log2(e)/T computed on pre-scaled bf16 z (HMMA, f32 acc).
// Per row: m = max_j, s = sum_j 2^(v-m), t = v[i,(i+B)%2B]; loss = ln2*(m+log2 s-t).

#define NTOT   8192
#define BHALF  4096
#define DK     128
#define TM     128
#define TNJ    128              // cols per j-tile
#define NJT    32               // j-tiles per CTA (4096/128)
#define RS     272              // smem row stride bytes (128 bf16 + 8 pad)
#define SCALE_B2 2.68579530f    // sqrt(log2(e)/0.2)
#define LN2      0.69314718055994531f
#define SKIP_THR 40.0f

__device__ __align__(16) __nv_bfloat16 g_zb[NTOT * DK];
__device__ float g_m[4 * NTOT];   // partials: p = half*2 + wn
__device__ float g_s[4 * NTOT];
__device__ float g_t[4 * NTOT];

// ---------------------------------------------------------------------------
__global__ void prep_kernel(const float* __restrict__ z1,
                            const float* __restrict__ z2) {
    int idx = blockIdx.x * blockDim.x + threadIdx.x;      // float4 index
    const int half4 = BHALF * DK / 4;
    float4 v = (idx < half4) ? ((const float4*)z1)[idx]
                             : ((const float4*)z2)[idx - half4];
    __nv_bfloat162 lo = __floats2bfloat162_rn(v.x * SCALE_B2, v.y * SCALE_B2);
    __nv_bfloat162 hi = __floats2bfloat162_rn(v.z * SCALE_B2, v.w * SCALE_B2);
    __nv_bfloat162* o = (__nv_bfloat162*)&g_zb[idx * 4];
    o[0] = lo; o[1] = hi;
}

// ---------------------------------------------------------------------------
__device__ __forceinline__ float ex2f(float x) {
    float y; asm("ex2.approx.ftz.f32 %0, %1;" : "=f"(y) : "f"(x)); return y;
}
__device__ __forceinline__ uint32_t smem_u32(const void* p) {
    uint32_t a;
    asm("{ .reg .u64 t; cvta.to.shared.u64 t, %1; cvt.u32.u64 %0, t; }"
        : "=r"(a) : "l"(p));
    return a;
}
__device__ __forceinline__ void cp16(uint32_t dst, const void* src) {
    asm volatile("cp.async.cg.shared.global [%0], [%1], 16;"
                 :: "r"(dst), "l"(src) : "memory");
}
__device__ __forceinline__ uint32_t lds32(uint32_t a) {
    uint32_t v; asm volatile("ld.shared.b32 %0, [%1];" : "=r"(v) : "r"(a)); return v;
}
__device__ __forceinline__ void mma16816(float* c, const uint32_t* a,
                                         uint32_t b0, uint32_t b1) {
    asm volatile(
        "mma.sync.aligned.m16n8k16.row.col.f32.bf16.bf16.f32 "
        "{%0,%1,%2,%3}, {%4,%5,%6,%7}, {%8,%9}, {%0,%1,%2,%3};"
        : "+f"(c[0]), "+f"(c[1]), "+f"(c[2]), "+f"(c[3])
        : "r"(a[0]), "r"(a[1]), "r"(a[2]), "r"(a[3]), "r"(b0), "r"(b1));
}

// ---------------------------------------------------------------------------
// 128 CTAs x 256 threads. CTA b: rows (b>>1)*128, col half (b&1)*4096.
// smem: A tile [128][RS], B double buffer 2x[128][RS].
// Warp w: wm=w&3 row block (32 rows), wn=w>>2 col block (64 cols).
// ---------------------------------------------------------------------------
__global__ __launch_bounds__(256, 1) void ntxent_kernel() {
    extern __shared__ char smc[];
    const uint32_t smb = smem_u32(smc);
    const int tid  = threadIdx.x;
    const int wid  = tid >> 5;
    const int lane = tid & 31;
    const int q = lane & 3, g = lane >> 2;
    const int wm = wid & 3, wn = wid >> 2;
    const int i0 = (int)(blockIdx.x >> 1) * TM;
    const int half = blockIdx.x & 1;
    const int jh = half * BHALF;

    const uint32_t sA  = smb;
    const uint32_t sB0 = smb + 128 * RS;
    const uint32_t sB1 = sB0 + 128 * RS;

    // Prologue: A tile + B tile 0 (group 0). 2048 16B chunks each / 256 thr.
    #pragma unroll
    for (int k = 0; k < 8; ++k) {
        int u = tid + k * 256;
        int row = u >> 4, c = u & 15;
        cp16(sA + row * RS + c * 16, &g_zb[(i0 + row) * DK + c * 8]);
    }
    #pragma unroll
    for (int k = 0; k < 8; ++k) {
        int u = tid + k * 256;
        int row = u >> 4, c = u & 15;
        cp16(sB0 + row * RS + c * 16, &g_zb[(jh + row) * DK + c * 8]);
    }
    asm volatile("cp.async.commit_group;" ::: "memory");

    float rm[4], rs[4], tv[4];
    #pragma unroll
    for (int r = 0; r < 4; ++r) { rm[r] = -INFINITY; rs[r] = 0.f; tv[r] = -INFINITY; }

    // Per-thread static row ids (4 rows owned in every tile)
    int rowid[4];
    #pragma unroll
    for (int rr = 0; rr < 4; ++rr)
        rowid[rr] = i0 + wm * 32 + (rr >> 1) * 16 + (rr & 1) * 8 + g;

    for (int jt = 0; jt < NJT; ++jt) {
        asm volatile("cp.async.wait_group 0;" ::: "memory");
        __syncthreads();

        if (jt + 1 < NJT) {
            uint32_t nb = ((jt + 1) & 1) ? sB1 : sB0;
            int jr0 = jh + (jt + 1) * TNJ;
            #pragma unroll
            for (int k = 0; k < 8; ++k) {
                int u = tid + k * 256;
                int row = u >> 4, c = u & 15;
                cp16(nb + row * RS + c * 16, &g_zb[(jr0 + row) * DK + c * 8]);
            }
            asm volatile("cp.async.commit_group;" ::: "memory");
        }

        const uint32_t bb = (jt & 1) ? sB1 : sB0;
        float acc[2][8][4];
        #pragma unroll
        for (int mt = 0; mt < 2; ++mt)
            #pragma unroll
            for (int nt = 0; nt < 8; ++nt)
                #pragma unroll
                for (int c = 0; c < 4; ++c) acc[mt][nt][c] = 0.f;

        #pragma unroll
        for (int ks = 0; ks < 8; ++ks) {
            uint32_t a[2][4];
            #pragma unroll
            for (int mt = 0; mt < 2; ++mt) {
                uint32_t ra = sA + (wm * 32 + mt * 16 + g) * RS + ks * 32 + q * 4;
                a[mt][0] = lds32(ra);
                a[mt][1] = lds32(ra + 8 * RS);
                a[mt][2] = lds32(ra + 16);
                a[mt][3] = lds32(ra + 8 * RS + 16);
            }
            #pragma unroll
            for (int nt = 0; nt < 8; ++nt) {
                uint32_t rb = bb + (wn * 64 + nt * 8 + g) * RS + ks * 32 + q * 4;
                uint32_t b0 = lds32(rb);
                uint32_t b1 = lds32(rb + 16);
                mma16816(acc[0][nt], a[0], b0, b1);
                mma16816(acc[1][nt], a[1], b0, b1);
            }
        }

        // Fused epilogue: online (m, s) per owned row; rare diag/target fixup.
        int jbase = jh + jt * TNJ + wn * 64;
        #pragma unroll
        for (int rr = 0; rr < 4; ++rr) {
            const int mt = rr >> 1, o = (rr & 1) * 2;
            const int r = rowid[rr];
            float v[16];
            #pragma unroll
            for (int nt = 0; nt < 8; ++nt) {
                v[2 * nt]     = acc[mt][nt][o];
                v[2 * nt + 1] = acc[mt][nt][o + 1];
            }
            int tcol = (r + BHALF) & (NTOT - 1);
            if ((unsigned)(r - jbase) < 64u || (unsigned)(tcol - jbase) < 64u) {
                #pragma unroll
                for (int e = 0; e < 16; ++e) {
                    int j = jbase + (e >> 1) * 8 + 2 * q + (e & 1);
                    if (j == tcol) tv[rr] = v[e];
                    if (j == r)    v[e] = -INFINITY;   // diag mask
                }
            }
            float m0 = fmaxf(v[0], v[1]),   m1 = fmaxf(v[2], v[3]);
            float m2 = fmaxf(v[4], v[5]),   m3 = fmaxf(v[6], v[7]);
            float m4 = fmaxf(v[8], v[9]),   m5 = fmaxf(v[10], v[11]);
            float m6 = fmaxf(v[12], v[13]), m7 = fmaxf(v[14], v[15]);
            float mx = fmaxf(fmaxf(fmaxf(m0, m1), fmaxf(m2, m3)),
                             fmaxf(fmaxf(m4, m5), fmaxf(m6, m7)));
            if (mx > rm[rr] - SKIP_THR) {
                float mn = fmaxf(rm[rr], mx);
                float a0 = rs[rr] * ex2f(rm[rr] - mn);
                float a1 = 0.f, a2 = 0.f, a3 = 0.f;
                #pragma unroll
                for (int e = 0; e < 16; e += 4) {
                    a0 += ex2f(v[e]     - mn);
                    a1 += ex2f(v[e + 1] - mn);
                    a2 += ex2f(v[e + 2] - mn);
                    a3 += ex2f(v[e + 3] - mn);
                }
                rs[rr] = (a0 + a1) + (a2 + a3);
                rm[rr] = mn;
            }
        }
    }

    // Quad reduction (lanes q=0..3 share the same rows, disjoint cols).
    #pragma unroll
    for (int off = 1; off <= 2; off <<= 1) {
        #pragma unroll
        for (int rr = 0; rr < 4; ++rr) {
            float m2 = __shfl_xor_sync(0xffffffffu, rm[rr], off);
            float s2 = __shfl_xor_sync(0xffffffffu, rs[rr], off);
            float t2 = __shfl_xor_sync(0xffffffffu, tv[rr], off);
            float nm = fmaxf(rm[rr], m2);
            rs[rr] = rs[rr] * ex2f(rm[rr] - nm) + s2 * ex2f(m2 - nm);
            rm[rr] = nm;
            tv[rr] = fmaxf(tv[rr], t2);
        }
    }
    if (q == 0) {
        int p = half * 2 + wn;
        #pragma unroll
        for (int rr = 0; rr < 4; ++rr) {
            int idx = p * NTOT + rowid[rr];
            g_m[idx] = rm[rr];
            g_s[idx] = rs[rr];
            g_t[idx] = tv[rr];
        }
    }
}

// ---------------------------------------------------------------------------
__global__ void combine_kernel(float* __restrict__ out) {
    __shared__ float red[256];
    int tid = threadIdx.x;
    float acc = 0.0f;
    for (int i = tid; i < NTOT; i += 256) {
        float m = -INFINITY, t = -INFINITY;
        #pragma unroll
        for (int p = 0; p < 4; ++p) {
            m = fmaxf(m, g_m[p * NTOT + i]);
            t = fmaxf(t, g_t[p * NTOT + i]);
        }
        float s = 0.0f;
        #pragma unroll
        for (int p = 0; p < 4; ++p)
            s += g_s[p * NTOT + i] * exp2f(g_m[p * NTOT + i] - m);
        acc += (m + log2f(s) - t);
    }
    red[tid] = acc;
    __syncthreads();
    for (int st = 128; st > 0; st >>= 1) {
        if (tid < st) red[tid] += red[tid + st];
        __syncthreads();
    }
    if (tid == 0) out[0] = red[0] * (LN2 / (float)NTOT);
}

// ---------------------------------------------------------------------------
extern "C" void kernel_launch(void* const* d_in, const int* in_sizes, int n_in,
                              void* d_out, int out_size) {
    const float* z1 = (const float*)d_in[0];
    const float* z2 = (const float*)d_in[1];
    float* out = (float*)d_out;

    const int smem_bytes = 3 * 128 * RS;   // 104448 B
    cudaFuncSetAttribute(ntxent_kernel,
                         cudaFuncAttributeMaxDynamicSharedMemorySize, smem_bytes);

    prep_kernel<<<(NTOT * DK / 4) / 256, 256>>>(z1, z2);
    ntxent_kernel<<<NTOT / TM * 2, 256, smem_bytes>>>();
    combine_kernel<<<1, 256>>>(out);
}